// round 8
// baseline (speedup 1.0000x reference)
#include <cuda_runtime.h>
#include <cuda_fp16.h>

#define LUT5 59049      // 9^5
#define HW   (1024*1024)
#define NPIX (4*HW)

#define BLK     512         // 8^3 base-index blocks over dims 2,3,4
#define NENT    (81*BLK)    // 41472 entries
// Entry: 40 fp16 (5 ch x 8 corners of dims 2,3,4), padded to 128B stride (one line).
// Half index within entry: c*8 + t, t = c2*4 + c3*2 + c4. Halves 40..63 unused (zero).
__device__ __align__(128) __half g_D[NENT * 64];   // 5.3 MB

__global__ void pack_kernel(const float* __restrict__ lut) {
    int tid = blockIdx.x * blockDim.x + threadIdx.x;
    if (tid >= NENT * 5) return;
    int c = tid / NENT;
    int e = tid - c * NENT;
    int i01 = e >> 9;            // 0..80
    int rem = e & 511;
    int b2 = rem >> 6, b3 = (rem >> 3) & 7, b4 = rem & 7;
    int i0 = i01 / 9, i1 = i01 - (i01 / 9) * 9;
    const float* src = lut + c * LUT5 + i0 * 6561 + i1 * 729 + b2 * 81 + b3 * 9 + b4;

    __half2 h0 = __floats2half2_rn(src[0],  src[1]);    // c2=0 c3=0
    __half2 h1 = __floats2half2_rn(src[9],  src[10]);   // c2=0 c3=1
    __half2 h2 = __floats2half2_rn(src[81], src[82]);   // c2=1 c3=0
    __half2 h3 = __floats2half2_rn(src[90], src[91]);   // c2=1 c3=1

    uint4 v;
    v.x = *(unsigned*)&h0;  v.y = *(unsigned*)&h1;
    v.z = *(unsigned*)&h2;  v.w = *(unsigned*)&h3;
    *(uint4*)(g_D + (size_t)e * 64 + c * 8) = v;   // 16B-aligned dst
}

__device__ __forceinline__ uint4 ldg_cg(const uint4* p) {
    uint4 v;
    asm volatile("ld.global.cg.v4.u32 {%0,%1,%2,%3}, [%4];"
                 : "=r"(v.x), "=r"(v.y), "=r"(v.z), "=r"(v.w) : "l"(p));
    return v;
}

__device__ __forceinline__ float dot8h(uint4 q, __half2 w0, __half2 w1,
                                       __half2 w2, __half2 w3) {
    __half2 s = __hmul2(*(const __half2*)&q.x, w0);
    s = __hfma2(*(const __half2*)&q.y, w1, s);
    s = __hfma2(*(const __half2*)&q.z, w2, s);
    s = __hfma2(*(const __half2*)&q.w, w3, s);
    float2 f = __half22float2(s);
    return f.x + f.y;
}

// Warp owns 32 consecutive pixels. Coalesced streaming I/O, 6 compute batches of
// 5-lane groups, shfl redistribution. Gathers bypass L1 allocation (.cg).
__global__ void __launch_bounds__(256, 6)
lut_kernel(const float* __restrict__ x, float* __restrict__ out) {
    const unsigned FULL = 0xffffffffu;
    int lane = threadIdx.x & 31;
    int gw   = (blockIdx.x * blockDim.x + threadIdx.x) >> 5;
    int p    = gw * 32 + lane;              // this lane's owned pixel
    int b    = p >> 20;
    int hw   = p & (HW - 1);
    size_t iobase = (size_t)b * 5 * HW + hw;   // warp-aligned: hw ≡ lane (mod 32)

    float xs0 = fminf(fmaxf(__ldcs(x + iobase + 0 * (size_t)HW) * 8.0f, 0.0f), 7.9999995f);
    float xs1 = fminf(fmaxf(__ldcs(x + iobase + 1 * (size_t)HW) * 8.0f, 0.0f), 7.9999995f);
    float xs2 = fminf(fmaxf(__ldcs(x + iobase + 2 * (size_t)HW) * 8.0f, 0.0f), 7.9999995f);
    float xs3 = fminf(fmaxf(__ldcs(x + iobase + 3 * (size_t)HW) * 8.0f, 0.0f), 7.9999995f);
    float xs4 = fminf(fmaxf(__ldcs(x + iobase + 4 * (size_t)HW) * 8.0f, 0.0f), 7.9999995f);

    int g  = lane / 5; if (g > 5) g = 5;    // compute group 0..5
    int ch = lane - g * 5;
    int che = ch > 4 ? 4 : ch;
    int myk = lane / 6;                      // batch in which this lane's pixel is computed
    int gs  = lane - myk * 6;                // its group index in that batch

    const uint4* Dq = (const uint4*)g_D;
    float ores[5];

#pragma unroll
    for (int k = 0; k < 6; k++) {
        int q = 6 * k + g;                   // pixel-in-warp this group handles
        bool active = q < 32;                // batch 5: only groups 0,1 real
        int qs = active ? q : 31;

        float v0 = __shfl_sync(FULL, xs0, qs);
        float v1 = __shfl_sync(FULL, xs1, qs);
        float v2 = __shfl_sync(FULL, xs2, qs);
        float v3 = __shfl_sync(FULL, xs3, qs);
        float v4 = __shfl_sync(FULL, xs4, qs);

        float f0 = floorf(v0), f1 = floorf(v1), f2 = floorf(v2),
              f3 = floorf(v3), f4 = floorf(v4);
        int i0 = (int)f0, i1 = (int)f1, i2 = (int)f2, i3 = (int)f3, i4 = (int)f4;
        float fr0 = v0 - f0, fr1 = v1 - f1, fr2 = v2 - f2,
              fr3 = v3 - f3, fr4 = v4 - f4;

        int ent = ((i0 * 9 + i1) << 9) + (i2 << 6) + (i3 << 3) + i4;

        float w0a = 1.0f - fr0, w0b = fr0;
        float w1a = 1.0f - fr1, w1b = fr1;
        float w2a = 1.0f - fr2, w2b = fr2;
        float w3a = 1.0f - fr3, w3b = fr3;
        float w4a = 1.0f - fr4, w4b = fr4;

        float pw0 = w0a * w1a, pw1 = w0a * w1b, pw2 = w0b * w1a, pw3 = w0b * w1b;
        float t0 = w2a * w3a, t1 = w2a * w3b, t2 = w2b * w3a, t3 = w2b * w3b;

        __half2 cw0 = __floats2half2_rn(t0 * w4a, t0 * w4b);
        __half2 cw1 = __floats2half2_rn(t1 * w4a, t1 * w4b);
        __half2 cw2 = __floats2half2_rn(t2 * w4a, t2 * w4b);
        __half2 cw3 = __floats2half2_rn(t3 * w4a, t3 * w4b);

        float acc = 0.0f;
        if (active) {
            uint4 q0 = ldg_cg(Dq + (ent)            * 8 + che);
            uint4 q1 = ldg_cg(Dq + (ent + BLK)      * 8 + che);
            uint4 q2 = ldg_cg(Dq + (ent + 9 * BLK)  * 8 + che);
            uint4 q3 = ldg_cg(Dq + (ent + 10 * BLK) * 8 + che);
            acc = pw0 * dot8h(q0, cw0, cw1, cw2, cw3);
            acc = fmaf(pw1, dot8h(q1, cw0, cw1, cw2, cw3), acc);
            acc = fmaf(pw2, dot8h(q2, cw0, cw1, cw2, cw3), acc);
            acc = fmaf(pw3, dot8h(q3, cw0, cw1, cw2, cw3), acc);
        }

        // Scatter this batch's 6 pixels x 5 channels back to owner lanes.
        bool mine = (k == myk);
#pragma unroll
        for (int c = 0; c < 5; c++) {
            float s = __shfl_sync(FULL, acc, (gs * 5 + c) & 31);
            if (mine) ores[c] = s;
        }
    }

    // Coalesced streaming stores: one aligned 128B line per channel plane.
    __stcs(out + iobase + 0 * (size_t)HW, ores[0]);
    __stcs(out + iobase + 1 * (size_t)HW, ores[1]);
    __stcs(out + iobase + 2 * (size_t)HW, ores[2]);
    __stcs(out + iobase + 3 * (size_t)HW, ores[3]);
    __stcs(out + iobase + 4 * (size_t)HW, ores[4]);
}

extern "C" void kernel_launch(void* const* d_in, const int* in_sizes, int n_in,
                              void* d_out, int out_size) {
    const float* x   = (const float*)d_in[0];
    const float* lut = (const float*)d_in[1];
    if (n_in >= 2 && in_sizes[0] == 5 * LUT5) {
        lut = (const float*)d_in[0];
        x   = (const float*)d_in[1];
    }
    float* out = (float*)d_out;

    pack_kernel<<<(NENT * 5 + 255) / 256, 256>>>(lut);

    int blocks = NPIX / (32 * 8);   // 32 px/warp, 8 warps/block
    lut_kernel<<<blocks, 256>>>(x, out);
}